// round 1
// baseline (speedup 1.0000x reference)
#include <cuda_runtime.h>
#include <cuda_bf16.h>
#include <math.h>

#define N_NODES 19
#define N_T     4096
#define LATENT  512
#define HID     2048
#define N_EDGES 342

// ---------------- scratch (no allocations allowed -> __device__ globals) ----
__device__ float g_x1[N_NODES * LATENT];   // agg1 output
__device__ float g_t1[N_NODES * HID];      // relu(x1@W1a+b1a)
__device__ float g_h1[N_NODES * HID];      // relu( t1@W1b+b1b )
__device__ float g_x2[N_NODES * HID];      // agg2 output
__device__ float g_h4[N_NODES * N_T];      // relu(x2@W2a+b2a)
__device__ float g_recon[N_NODES * N_T];   // h4@W2b+b2b
__device__ float g_acc[N_NODES * N_T];     // split-K accumulator (max size)
__device__ float g_v[LATENT];              // flat@Wc1 accumulator

// ---------------- utility ---------------------------------------------------
__global__ void zero_kernel(float* __restrict__ p, int n) {
    int i = blockIdx.x * blockDim.x + threadIdx.x;
    if (i < n) p[i] = 0.0f;
}

// ---------------- GIN aggregation: out = h + segment_sum(h[src], dst) -------
// edge buffer may be int64 or int32 (JAX x64 ambiguity) -> runtime detect.
__global__ void agg_kernel(const float* __restrict__ h,
                           const void* __restrict__ eidx,
                           float* __restrict__ out, int C) {
    int node = blockIdx.x;
    int c = blockIdx.y * blockDim.x + threadIdx.x;
    if (c >= C) return;

    // detect element width: if data is int32, reading as int64 combines two
    // small indices -> value >= 2^32 whenever the high half is nonzero.
    const long long* e64 = (const long long*)eidx;
    bool i64 = true;
    for (int i = 0; i < N_EDGES; ++i) {
        long long v = e64[i];
        if (v < 0 || v >= N_NODES) { i64 = false; break; }
    }
    const int* e32 = (const int*)eidx;

    float acc = h[node * C + c];
    for (int e = 0; e < N_EDGES; ++e) {
        int d = i64 ? (int)e64[N_EDGES + e] : e32[N_EDGES + e];
        if (d == node) {
            int s = i64 ? (int)e64[e] : e32[e];
            acc += h[s * C + c];
        }
    }
    out[node * C + c] = acc;
}

// ---------------- split-K GEMM partial: Cacc += A[19,K] @ W[K,N] ------------
// Block: 128 threads x 2 cols = 256-column tile; grid.y = K/kchunk slabs.
// A slab is staged into shared pre-duplicated as {a,a} pairs so the inner
// loop is pure LDS.64(broadcast) + fma.rn.f32x2 (packed, 2 MACs/issue).
__global__ __launch_bounds__(128) void gemm_partial(
        const float* __restrict__ A, const float* __restrict__ W,
        float* __restrict__ Cacc, int K, int N, int kchunk) {
    __shared__ unsigned long long sA[N_NODES * 64];

    int col  = blockIdx.x * 256 + threadIdx.x * 2;
    int kbeg = blockIdx.y * kchunk;
    int kend = kbeg + kchunk; // all K divisible by kchunk by construction

    unsigned long long acc[N_NODES];
#pragma unroll
    for (int r = 0; r < N_NODES; ++r) acc[r] = 0ull;

    for (int k0 = kbeg; k0 < kend; k0 += 64) {
        // stage A[:, k0:k0+64] as duplicated pairs
        for (int i = threadIdx.x; i < N_NODES * 64; i += 128) {
            int r = i >> 6, k = i & 63;
            float a = A[r * K + k0 + k];
            unsigned long long p;
            asm("mov.b64 %0, {%1, %1};" : "=l"(p) : "f"(a));
            sA[i] = p;
        }
        __syncthreads();

        const float* Wp = W + (size_t)k0 * N + col;
#pragma unroll 4
        for (int kk = 0; kk < 64; ++kk) {
            unsigned long long w =
                *reinterpret_cast<const unsigned long long*>(Wp);
            Wp += N;
#pragma unroll
            for (int r = 0; r < N_NODES; ++r) {
                asm("fma.rn.f32x2 %0, %1, %2, %0;"
                    : "+l"(acc[r]) : "l"(sA[r * 64 + kk]), "l"(w));
            }
        }
        __syncthreads();
    }

#pragma unroll
    for (int r = 0; r < N_NODES; ++r) {
        float2 v = *reinterpret_cast<float2*>(&acc[r]);
        atomicAdd(&Cacc[r * N + col],     v.x);
        atomicAdd(&Cacc[r * N + col + 1], v.y);
    }
}

// ---------------- epilogue: out = [relu](acc + bias), optional 2nd copy -----
__global__ void epilogue_kernel(const float* __restrict__ acc,
                                const float* __restrict__ bias,
                                float* __restrict__ out,
                                float* __restrict__ out2,
                                int nmask, int total, int do_relu) {
    int i = blockIdx.x * blockDim.x + threadIdx.x;
    if (i >= total) return;
    float v = acc[i] + bias[i & nmask];
    if (do_relu) v = fmaxf(v, 0.0f);
    out[i] = v;
    if (out2) out2[i] = v;
}

// ---------------- classifier FC1: v[512] = flat[77824] @ Wc1[77824,512] -----
// Rank-1 accumulation: block streams a row range, thread j owns column j
// (fully coalesced 2KB row reads), then one atomicAdd per (block, j).
__global__ __launch_bounds__(512) void fc1_kernel(
        const float* __restrict__ flat, const float* __restrict__ Wc1,
        float* __restrict__ v) {
    const int ROWS = N_NODES * N_T;
    int j = threadIdx.x;
    int rows_per = (ROWS + gridDim.x - 1) / gridDim.x;
    int r0 = blockIdx.x * rows_per;
    int r1 = min(r0 + rows_per, ROWS);
    float acc = 0.0f;
    int i = r0;
#pragma unroll 1
    for (; i + 8 <= r1; i += 8) {
#pragma unroll
        for (int u = 0; u < 8; ++u)
            acc += flat[i + u] * Wc1[(size_t)(i + u) * LATENT + j];
    }
    for (; i < r1; ++i)
        acc += flat[i] * Wc1[(size_t)i * LATENT + j];
    atomicAdd(&v[j], acc);
}

// ---------------- classifier FC2 + sigmoid ----------------------------------
__global__ void fc2_kernel(const float* __restrict__ v,
                           const float* __restrict__ bc1,
                           const float* __restrict__ Wc2,
                           const float* __restrict__ bc2,
                           float* __restrict__ out) {
    __shared__ float red[LATENT];
    int j = threadIdx.x;
    red[j] = (v[j] + bc1[j]) * Wc2[j];
    __syncthreads();
    for (int s = LATENT / 2; s > 0; s >>= 1) {
        if (j < s) red[j] += red[j + s];
        __syncthreads();
    }
    if (j == 0) out[0] = 1.0f / (1.0f + expf(-(red[0] + bc2[0])));
}

// ---------------- launch ----------------------------------------------------
extern "C" void kernel_launch(void* const* d_in, const int* in_sizes, int n_in,
                              void* d_out, int out_size) {
    const float* z    = (const float*)d_in[0];
    const void*  eidx = d_in[1];
    const float* W1a  = (const float*)d_in[2];
    const float* b1a  = (const float*)d_in[3];
    const float* W1b  = (const float*)d_in[4];
    const float* b1b  = (const float*)d_in[5];
    const float* W2a  = (const float*)d_in[6];
    const float* b2a  = (const float*)d_in[7];
    const float* W2b  = (const float*)d_in[8];
    const float* b2b  = (const float*)d_in[9];
    const float* Wc1  = (const float*)d_in[10];
    const float* bc1  = (const float*)d_in[11];
    const float* Wc2  = (const float*)d_in[12];
    const float* bc2  = (const float*)d_in[13];
    float* out = (float*)d_out;

    float *x1, *t1, *h1, *x2, *h4, *recon, *acc, *v;
    cudaGetSymbolAddress((void**)&x1,    g_x1);
    cudaGetSymbolAddress((void**)&t1,    g_t1);
    cudaGetSymbolAddress((void**)&h1,    g_h1);
    cudaGetSymbolAddress((void**)&x2,    g_x2);
    cudaGetSymbolAddress((void**)&h4,    g_h4);
    cudaGetSymbolAddress((void**)&recon, g_recon);
    cudaGetSymbolAddress((void**)&acc,   g_acc);
    cudaGetSymbolAddress((void**)&v,     g_v);

    const int nHID = N_NODES * HID;   // 38912
    const int nNT  = N_NODES * N_T;   // 77824

    // ---- GIN layer 1 ----
    agg_kernel<<<dim3(N_NODES, LATENT / 256), 256>>>(z, eidx, x1, LATENT);

    zero_kernel<<<(nHID + 255) / 256, 256>>>(acc, nHID);
    gemm_partial<<<dim3(HID / 256, 4), 128>>>(x1, W1a, acc, LATENT, HID, 128);
    epilogue_kernel<<<(nHID + 255) / 256, 256>>>(acc, b1a, t1, nullptr,
                                                 HID - 1, nHID, 1);

    zero_kernel<<<(nHID + 255) / 256, 256>>>(acc, nHID);
    gemm_partial<<<dim3(HID / 256, 32), 128>>>(t1, W1b, acc, HID, HID, 64);
    epilogue_kernel<<<(nHID + 255) / 256, 256>>>(acc, b1b, h1, nullptr,
                                                 HID - 1, nHID, 1);

    // ---- GIN layer 2 ----
    agg_kernel<<<dim3(N_NODES, HID / 256), 256>>>(h1, eidx, x2, HID);

    zero_kernel<<<(nNT + 255) / 256, 256>>>(acc, nNT);
    gemm_partial<<<dim3(N_T / 256, 16), 128>>>(x2, W2a, acc, HID, N_T, 128);
    epilogue_kernel<<<(nNT + 255) / 256, 256>>>(acc, b2a, h4, nullptr,
                                                N_T - 1, nNT, 1);

    zero_kernel<<<(nNT + 255) / 256, 256>>>(acc, nNT);
    zero_kernel<<<2, 256>>>(v, LATENT);
    gemm_partial<<<dim3(N_T / 256, 32), 128>>>(h4, W2b, acc, N_T, N_T, 128);
    // recon goes to both scratch (for FC1) and the output tensor (out[1:])
    epilogue_kernel<<<(nNT + 255) / 256, 256>>>(acc, b2b, recon, out + 1,
                                                N_T - 1, nNT, 0);

    // ---- classifier ----
    fc1_kernel<<<304, 512>>>(recon, Wc1, v);
    fc2_kernel<<<1, LATENT>>>(v, bc1, Wc2, bc2, out);
}